// round 2
// baseline (speedup 1.0000x reference)
#include <cuda_runtime.h>
#include <math.h>

#define H 512
#define HEADS 8
#define DK 64
#define NCLASS 4
#define VOCAB 5000
#define LW 32
#define NLEAF 20000
#define NPAR 20000
#define NTOT (NLEAF + NPAR)
#define DEG 4
#define NLAYER 5
#define MAXB 64

// ---- static device scratch (no allocations allowed) ----
__device__ float g_Et[VOCAB * H];        // E_bu transposed [VOCAB, H]
__device__ float g_xe[NTOT * H];         // per-node embedding sum
__device__ float g_gz[NPAR * H];         // W_z@xe_p + b_z
__device__ float g_gr[NPAR * H];
__device__ float g_gh[NPAR * H];
__device__ float g_ph[NPAR * H];         // parent hidden states
__device__ volatile int g_done[NPAR];    // ready flags
__device__ float g_pmax[MAXB * H];       // partial column maxes

// ============================================================
// prep: transpose E_bu -> g_Et, zero done flags
// ============================================================
__global__ void prep_kernel(const float* __restrict__ E_bu) {
    int idx = blockIdx.x * 256 + threadIdx.x;
    if (idx < VOCAB * H) {
        int v = idx / H, h = idx - v * H;
        g_Et[idx] = E_bu[h * VOCAB + v];
    }
    if (idx < NPAR) g_done[idx] = 0;
}

// ============================================================
// xe[n,:] = sum_l Et[idx[n,l], :] * w[n,l]
// ============================================================
__global__ __launch_bounds__(128) void xe_kernel(const float* __restrict__ xw,
                                                 const int* __restrict__ xi) {
    __shared__ float sw[LW];
    __shared__ int si[LW];
    int n = blockIdx.x;
    int t = threadIdx.x;
    if (t < LW) { sw[t] = xw[n * LW + t]; si[t] = xi[n * LW + t]; }
    __syncthreads();
    float4 acc = make_float4(0.f, 0.f, 0.f, 0.f);
#pragma unroll 8
    for (int l = 0; l < LW; l++) {
        float w = sw[l];
        const float4 e = *(const float4*)&g_Et[si[l] * H + t * 4];
        acc.x += w * e.x; acc.y += w * e.y; acc.z += w * e.z; acc.w += w * e.w;
    }
    *(float4*)&g_xe[n * H + t * 4] = acc;
}

// ============================================================
// g_g{z,r,h}[p,n] = bias[n] + sum_k g_xe[NLEAF+p,k] * B[n,k]
// 128x128 tile, BK=16, 256 threads, 8x8 per thread
// ============================================================
#define BM 128
#define BN 128
#define BK 16
__global__ __launch_bounds__(256) void sgemm_nt(const float* __restrict__ B,
                                                const float* __restrict__ bias,
                                                int which) {
    const int M = NPAR;
    const float* A = g_xe + NLEAF * H;
    float* C = (which == 0) ? g_gz : (which == 1) ? g_gr : g_gh;
    __shared__ float As[BK][BM];
    __shared__ float Bs[BK][BN];
    int row0 = blockIdx.x * BM;
    int n0 = blockIdx.y * BN;
    int tid = threadIdx.x;
    int tr = tid >> 4, tc = tid & 15;

    float acc[8][8];
#pragma unroll
    for (int i = 0; i < 8; i++)
#pragma unroll
        for (int j = 0; j < 8; j++) acc[i][j] = 0.f;

    for (int k0 = 0; k0 < H; k0 += BK) {
#pragma unroll
        for (int i = 0; i < 2; i++) {
            int li = tid + i * 256;
            int m = li >> 2, kq = li & 3;
            int row = row0 + m;
            float4 f = make_float4(0.f, 0.f, 0.f, 0.f);
            if (row < M) f = *(const float4*)&A[row * H + k0 + kq * 4];
            As[kq * 4 + 0][m] = f.x; As[kq * 4 + 1][m] = f.y;
            As[kq * 4 + 2][m] = f.z; As[kq * 4 + 3][m] = f.w;
        }
#pragma unroll
        for (int i = 0; i < 2; i++) {
            int li = tid + i * 256;
            int nn = li >> 2, kq = li & 3;
            float4 f = *(const float4*)&B[(n0 + nn) * H + k0 + kq * 4];
            Bs[kq * 4 + 0][nn] = f.x; Bs[kq * 4 + 1][nn] = f.y;
            Bs[kq * 4 + 2][nn] = f.z; Bs[kq * 4 + 3][nn] = f.w;
        }
        __syncthreads();
#pragma unroll
        for (int kk = 0; kk < BK; kk++) {
            float ra[8], rb[8];
#pragma unroll
            for (int i = 0; i < 8; i++) ra[i] = As[kk][tr * 8 + i];
#pragma unroll
            for (int j = 0; j < 8; j++) rb[j] = Bs[kk][tc * 8 + j];
#pragma unroll
            for (int i = 0; i < 8; i++)
#pragma unroll
                for (int j = 0; j < 8; j++) acc[i][j] += ra[i] * rb[j];
        }
        __syncthreads();
    }
#pragma unroll
    for (int i = 0; i < 8; i++) {
        int row = row0 + tr * 8 + i;
        if (row >= M) continue;
#pragma unroll
        for (int j = 0; j < 8; j++) {
            int col = n0 + tc * 8 + j;
            C[row * H + col] = acc[i][j] + bias[col];
        }
    }
}

// ============================================================
// Main dataflow kernel: one block per parent, spin on child flags.
// ============================================================
__global__ __launch_bounds__(256) void tree_kernel(const int* __restrict__ tree,
                                                   const float* __restrict__ Uz,
                                                   const float* __restrict__ Ur,
                                                   const float* __restrict__ Uh) {
    __shared__ float bufA[DEG][H];
    __shared__ float bufB[DEG][H];
    __shared__ float s_mem[H], zs[H], rs[H], mr[H];
    __shared__ float sc[HEADS][DEG][DEG];
    __shared__ int cidx[DEG];
    __shared__ int s_nc;

    int p = blockIdx.x;
    int tid = threadIdx.x;

    if (tid == 0) {
        int nc = 0;
        for (int j = 0; j < DEG; j++) {
            int c = tree[p * DEG + j];
            if (c > -1) cidx[nc++] = c;
        }
        s_nc = nc;
    }
    __syncthreads();
    int nc = s_nc;

    if (tid < nc) {
        int c = cidx[tid];
        if (c >= NLEAF) {
            while (g_done[c - NLEAF] == 0) { __nanosleep(64); }
        }
    }
    __threadfence();
    __syncthreads();

    for (int i = 0; i < nc; i++) {
        int c = cidx[i];
        const float* src = (c < NLEAF) ? &g_xe[c * H] : &g_ph[(c - NLEAF) * H];
        if (tid < 128) *(float4*)&bufA[i][tid * 4] = *(const float4*)&src[tid * 4];
    }
    __syncthreads();

    float (*cur)[H] = bufA;
    float (*nxt)[H] = bufB;

    if (nc > 0) {
        for (int layer = 0; layer < NLAYER; layer++) {
            int tot = HEADS * nc * nc;
            for (int t = tid; t < tot; t += 256) {
                int hd = t / (nc * nc);
                int r2 = t - hd * nc * nc;
                int q = r2 / nc, k = r2 - q * nc;
                const float* qp = &cur[q][hd * DK];
                const float* kp = &cur[k][hd * DK];
                float s = 0.f;
#pragma unroll 16
                for (int d = 0; d < DK; d++) s += qp[d] * kp[d];
                sc[hd][q][k] = s * 0.125f;
            }
            __syncthreads();
            for (int t = tid; t < HEADS * nc; t += 256) {
                int hd = t / nc, q = t - hd * nc;
                float m = -1e30f;
                for (int k = 0; k < nc; k++) m = fmaxf(m, sc[hd][q][k]);
                float ssum = 0.f;
                for (int k = 0; k < nc; k++) {
                    float e = expf(sc[hd][q][k] - m);
                    ssum += e;
                    sc[hd][q][k] = e;
                }
                float inv = 1.0f / ssum;
                for (int k = 0; k < nc; k++) sc[hd][q][k] *= inv;
            }
            __syncthreads();
            for (int c = tid; c < H; c += 256) {
                int hd = c >> 6;
                for (int q = 0; q < nc; q++) {
                    float o = 0.f;
                    for (int k = 0; k < nc; k++) o += sc[hd][q][k] * cur[k][c];
                    nxt[q][c] = o;
                }
            }
            __syncthreads();
            float (*tmp)[H] = cur; cur = nxt; nxt = tmp;
        }
        float invn = 1.0f / (float)nc;
        for (int c = tid; c < H; c += 256) {
            float s = 0.f;
            for (int q = 0; q < nc; q++) s += cur[q][c];
            s_mem[c] = s * invn;
        }
    } else {
        for (int c = tid; c < H; c += 256) s_mem[c] = 0.f;
    }
    __syncthreads();

    const float4* mem4 = (const float4*)s_mem;
    for (int rr = tid; rr < 2 * H; rr += 256) {
        int row = rr & (H - 1);
        const float* Urow = (rr < H) ? &Uz[row * H] : &Ur[row * H];
        float g = (rr < H) ? g_gz[p * H + row] : g_gr[p * H + row];
        const float4* u4 = (const float4*)Urow;
        float s0 = 0.f, s1 = 0.f, s2 = 0.f, s3 = 0.f;
#pragma unroll 8
        for (int k = 0; k < H / 4; k++) {
            float4 u = u4[k]; float4 m = mem4[k];
            s0 += u.x * m.x; s1 += u.y * m.y; s2 += u.z * m.z; s3 += u.w * m.w;
        }
        float s = (s0 + s1) + (s2 + s3) + g;
        float v = 1.0f / (1.0f + expf(-s));
        if (rr < H) zs[row] = v; else rs[row] = v;
    }
    __syncthreads();
    for (int c = tid; c < H; c += 256) mr[c] = s_mem[c] * rs[c];
    __syncthreads();

    const float4* mr4 = (const float4*)mr;
    for (int row = tid; row < H; row += 256) {
        const float4* u4 = (const float4*)&Uh[row * H];
        float s0 = 0.f, s1 = 0.f, s2 = 0.f, s3 = 0.f;
#pragma unroll 8
        for (int k = 0; k < H / 4; k++) {
            float4 u = u4[k]; float4 m = mr4[k];
            s0 += u.x * m.x; s1 += u.y * m.y; s2 += u.z * m.z; s3 += u.w * m.w;
        }
        float cc = tanhf((s0 + s1) + (s2 + s3) + g_gh[p * H + row]);
        float z = zs[row];
        g_ph[p * H + row] = z * s_mem[row] + (1.0f - z) * cc;
    }

    __threadfence();
    __syncthreads();
    if (tid == 0) g_done[p] = 1;
}

// ============================================================
__global__ void maxk_kernel() {
    int b = blockIdx.x;
    int rows_per = (NPAR + MAXB - 1) / MAXB;
    int r0 = b * rows_per;
    int r1 = min(NPAR, r0 + rows_per);
    for (int c = threadIdx.x; c < H; c += 256) {
        float m = -1e30f;
        for (int r = r0; r < r1; r++) m = fmaxf(m, g_ph[r * H + c]);
        g_pmax[b * H + c] = m;
    }
}

__global__ __launch_bounds__(512) void final_kernel(const float* __restrict__ Wout,
                                                    const float* __restrict__ bout,
                                                    float* __restrict__ out) {
    __shared__ float fin[H];
    __shared__ float logits[NCLASS];
    int tid = threadIdx.x;
    if (tid < H) {
        float m = -1e30f;
        for (int b = 0; b < MAXB; b++) m = fmaxf(m, g_pmax[b * H + tid]);
        fin[tid] = m;
    }
    __syncthreads();
    if (tid < NCLASS * 32) {
        int cls = tid >> 5, lane = tid & 31;
        float s = 0.f;
        for (int h = lane; h < H; h += 32) s += Wout[cls * H + h] * fin[h];
#pragma unroll
        for (int o = 16; o > 0; o >>= 1) s += __shfl_down_sync(0xffffffffu, s, o);
        if (lane == 0) logits[cls] = s + bout[cls];
    }
    __syncthreads();
    if (tid == 0) {
        float m = fmaxf(fmaxf(logits[0], logits[1]), fmaxf(logits[2], logits[3]));
        float e0 = expf(logits[0] - m), e1 = expf(logits[1] - m);
        float e2 = expf(logits[2] - m), e3 = expf(logits[3] - m);
        float inv = 1.0f / (e0 + e1 + e2 + e3);
        out[0] = e0 * inv; out[1] = e1 * inv; out[2] = e2 * inv; out[3] = e3 * inv;
    }
}

// ============================================================
extern "C" void kernel_launch(void* const* d_in, const int* in_sizes, int n_in,
                              void* d_out, int out_size) {
    const float* xw   = (const float*)d_in[0];
    const int*   xi   = (const int*)d_in[1];
    const int*   tree = (const int*)d_in[2];
    const float* E    = (const float*)d_in[3];
    const float* Uz   = (const float*)d_in[5];
    const float* bz   = (const float*)d_in[6];
    const float* Ur   = (const float*)d_in[8];
    const float* br   = (const float*)d_in[9];
    const float* Uh   = (const float*)d_in[11];
    const float* bh   = (const float*)d_in[12];
    const float* Wz   = (const float*)d_in[4];
    const float* Wr   = (const float*)d_in[7];
    const float* Wh   = (const float*)d_in[10];
    const float* Wout = (const float*)d_in[13];
    const float* bout = (const float*)d_in[14];

    prep_kernel<<<(VOCAB * H + 255) / 256, 256>>>(E);
    xe_kernel<<<NTOT, 128>>>(xw, xi);

    dim3 gg((NPAR + BM - 1) / BM, H / BN);
    sgemm_nt<<<gg, 256>>>(Wz, bz, 0);
    sgemm_nt<<<gg, 256>>>(Wr, br, 1);
    sgemm_nt<<<gg, 256>>>(Wh, bh, 2);

    tree_kernel<<<NPAR, 256>>>(tree, Uz, Ur, Uh);
    maxk_kernel<<<MAXB, 256>>>();
    final_kernel<<<1, 512>>>(Wout, bout, (float*)d_out);
    (void)in_sizes; (void)n_in; (void)out_size;
}

// round 3
// speedup vs baseline: 3.4378x; 3.4378x over previous
#include <cuda_runtime.h>
#include <math.h>

#define H 512
#define HEADS 8
#define DK 64
#define NCLASS 4
#define VOCAB 5000
#define LW 32
#define NLEAF 20000
#define NPAR 20000
#define NTOT (NLEAF + NPAR)
#define DEG 4
#define NLAYER 5
#define MAXB 64
#define MAXL 512

// ---- static device scratch ----
__device__ float g_Et[VOCAB * H];
__device__ float g_xe[NTOT * H];
__device__ float g_gz[NPAR * H];   // Wz@xe+bz, overwritten with z in B1
__device__ float g_gr[NPAR * H];   // Wr@xe+br, overwritten with mem*r in B1
__device__ float g_gh[NPAR * H];   // Wh@xe+bh
__device__ float g_mem[NPAR * H];  // attention-pooled memory per parent
__device__ float g_ph[NPAR * H];   // parent hidden states
__device__ float g_pmax[MAXB * H];

__device__ int g_lvl[NPAR];
__device__ int g_lstart[MAXL + 2];
__device__ int g_nlev;
__device__ int g_order[NPAR];

__device__ unsigned int g_bar_count;
__device__ volatile unsigned int g_bar_gen;

// ============================================================
__global__ void prep_kernel(const float* __restrict__ E_bu) {
    int idx = blockIdx.x * 256 + threadIdx.x;
    if (idx < VOCAB * H) {
        int v = idx / H, h = idx - v * H;
        g_Et[idx] = E_bu[h * VOCAB + v];
    }
    if (idx == 0) { g_bar_count = 0; g_bar_gen = 0; }
}

// ============================================================
__global__ __launch_bounds__(128) void xe_kernel(const float* __restrict__ xw,
                                                 const int* __restrict__ xi) {
    __shared__ float sw[LW];
    __shared__ int si[LW];
    int n = blockIdx.x;
    int t = threadIdx.x;
    if (t < LW) { sw[t] = xw[n * LW + t]; si[t] = xi[n * LW + t]; }
    __syncthreads();
    float4 acc = make_float4(0.f, 0.f, 0.f, 0.f);
#pragma unroll 8
    for (int l = 0; l < LW; l++) {
        float w = sw[l];
        const float4 e = *(const float4*)&g_Et[si[l] * H + t * 4];
        acc.x += w * e.x; acc.y += w * e.y; acc.z += w * e.z; acc.w += w * e.w;
    }
    *(float4*)&g_xe[n * H + t * 4] = acc;
}

// ============================================================
// W-GEMMs (independent half of GRU), 128x128 tile
// ============================================================
#define BM 128
#define BN 128
#define BK 16
__global__ __launch_bounds__(256) void sgemm_nt(const float* __restrict__ B,
                                                const float* __restrict__ bias,
                                                int which) {
    const int M = NPAR;
    const float* A = g_xe + NLEAF * H;
    float* C = (which == 0) ? g_gz : (which == 1) ? g_gr : g_gh;
    __shared__ float As[BK][BM];
    __shared__ float Bs[BK][BN];
    int row0 = blockIdx.x * BM;
    int n0 = blockIdx.y * BN;
    int tid = threadIdx.x;
    int tr = tid >> 4, tc = tid & 15;

    float acc[8][8];
#pragma unroll
    for (int i = 0; i < 8; i++)
#pragma unroll
        for (int j = 0; j < 8; j++) acc[i][j] = 0.f;

    for (int k0 = 0; k0 < H; k0 += BK) {
#pragma unroll
        for (int i = 0; i < 2; i++) {
            int li = tid + i * 256;
            int m = li >> 2, kq = li & 3;
            int row = row0 + m;
            float4 f = make_float4(0.f, 0.f, 0.f, 0.f);
            if (row < M) f = *(const float4*)&A[row * H + k0 + kq * 4];
            As[kq * 4 + 0][m] = f.x; As[kq * 4 + 1][m] = f.y;
            As[kq * 4 + 2][m] = f.z; As[kq * 4 + 3][m] = f.w;
        }
#pragma unroll
        for (int i = 0; i < 2; i++) {
            int li = tid + i * 256;
            int nn = li >> 2, kq = li & 3;
            float4 f = *(const float4*)&B[(n0 + nn) * H + k0 + kq * 4];
            Bs[kq * 4 + 0][nn] = f.x; Bs[kq * 4 + 1][nn] = f.y;
            Bs[kq * 4 + 2][nn] = f.z; Bs[kq * 4 + 3][nn] = f.w;
        }
        __syncthreads();
#pragma unroll
        for (int kk = 0; kk < BK; kk++) {
            float ra[8], rb[8];
#pragma unroll
            for (int i = 0; i < 8; i++) ra[i] = As[kk][tr * 8 + i];
#pragma unroll
            for (int j = 0; j < 8; j++) rb[j] = Bs[kk][tc * 8 + j];
#pragma unroll
            for (int i = 0; i < 8; i++)
#pragma unroll
                for (int j = 0; j < 8; j++) acc[i][j] += ra[i] * rb[j];
        }
        __syncthreads();
    }
#pragma unroll
    for (int i = 0; i < 8; i++) {
        int row = row0 + tr * 8 + i;
        if (row >= M) continue;
#pragma unroll
        for (int j = 0; j < 8; j++) {
            int col = n0 + tc * 8 + j;
            C[row * H + col] = acc[i][j] + bias[col];
        }
    }
}

// ============================================================
// Level computation + bucketing. Single block, 1024 threads.
// lvl lives in dynamic shared (80KB).
// ============================================================
extern __shared__ int s_dyn[];
__global__ void levels_kernel(const int* __restrict__ tree) {
    volatile int* lvl = s_dyn;
    int tid = threadIdx.x;
    int nt = blockDim.x;
    __shared__ int changed;
    __shared__ int s_maxl;
    __shared__ int cnt[MAXL + 1];

    for (int p = tid; p < NPAR; p += nt) lvl[p] = 1;
    if (tid == 0) s_maxl = 1;
    __syncthreads();

    for (int it = 0; it < 4096; it++) {
        if (tid == 0) changed = 0;
        __syncthreads();
        int ch = 0;
        for (int p = tid; p < NPAR; p += nt) {
            int4 t4 = ((const int4*)tree)[p];
            int m = 1;
            int c, v;
            c = t4.x; if (c >= NLEAF) { v = lvl[c - NLEAF] + 1; if (v > m) m = v; }
            c = t4.y; if (c >= NLEAF) { v = lvl[c - NLEAF] + 1; if (v > m) m = v; }
            c = t4.z; if (c >= NLEAF) { v = lvl[c - NLEAF] + 1; if (v > m) m = v; }
            c = t4.w; if (c >= NLEAF) { v = lvl[c - NLEAF] + 1; if (v > m) m = v; }
            if (m > lvl[p]) { lvl[p] = m; ch = 1; }
        }
        if (ch) changed = 1;
        __syncthreads();
        if (!changed) break;
    }

    for (int i = tid; i <= MAXL; i += nt) cnt[i] = 0;
    __syncthreads();
    int mymax = 1;
    for (int p = tid; p < NPAR; p += nt) {
        int l = lvl[p]; if (l > MAXL) l = MAXL;
        atomicAdd(&cnt[l], 1);
        if (l > mymax) mymax = l;
    }
    atomicMax(&s_maxl, mymax);
    __syncthreads();
    if (tid == 0) {
        int acc = 0;
        for (int l = 0; l <= MAXL; l++) { g_lstart[l] = acc; acc += cnt[l]; }
        g_lstart[MAXL + 1] = acc;
        g_nlev = s_maxl;
    }
    __syncthreads();
    for (int i = tid; i <= MAXL; i += nt) cnt[i] = g_lstart[i];
    __syncthreads();
    for (int p = tid; p < NPAR; p += nt) {
        int l = lvl[p]; if (l > MAXL) l = MAXL;
        int pos = atomicAdd(&cnt[l], 1);
        g_order[pos] = p;
        g_lvl[p] = l;
    }
}

// ============================================================
// Persistent wavefront kernel
// ============================================================
struct ShA {
    float bufA[DEG][H];
    float bufB[DEG][H];
    float sc[HEADS][DEG][DEG];
    int cidx[DEG];
    int nc;
};
struct ShB {
    float As[16][64];
    float Bs[16][128];
    int pidx[64];
};

__device__ __forceinline__ void grid_sync_dev(int nb) {
    __threadfence();
    __syncthreads();
    if (threadIdx.x == 0) {
        unsigned int mygen = g_bar_gen;
        unsigned int old = atomicAdd(&g_bar_count, 1u);
        if (old == (unsigned)nb - 1u) {
            g_bar_count = 0u;
            __threadfence();
            g_bar_gen = mygen + 1u;
        } else {
            while (g_bar_gen == mygen) __nanosleep(128);
        }
        __threadfence();
    }
    __syncthreads();
}

template <int PHASE>
__device__ __forceinline__ void gemm_tile(ShB* sb, int i0, int mtile, int j0,
                                          const float* __restrict__ Uz,
                                          const float* __restrict__ Ur,
                                          const float* __restrict__ Uh) {
    int tid = threadIdx.x;
    if (tid < 64) sb->pidx[tid] = (tid < mtile) ? g_order[i0 + tid] : 0;
    __syncthreads();

    const float* Asrc = (PHASE == 1) ? g_mem : g_gr;
    const float* Brow;
    if (PHASE == 1) Brow = (j0 < H) ? (Uz + (size_t)j0 * H) : (Ur + (size_t)(j0 - H) * H);
    else            Brow = Uh + (size_t)j0 * H;

    float acc[4][8];
#pragma unroll
    for (int a = 0; a < 4; a++)
#pragma unroll
        for (int b = 0; b < 8; b++) acc[a][b] = 0.f;

    int tr = tid >> 4, tc = tid & 15;

    for (int k0 = 0; k0 < H; k0 += 16) {
        {
            int i = tid >> 2, kq = tid & 3;
            float4 f = make_float4(0.f, 0.f, 0.f, 0.f);
            if (i < mtile) f = *(const float4*)&Asrc[(size_t)sb->pidx[i] * H + k0 + kq * 4];
            sb->As[kq * 4 + 0][i] = f.x; sb->As[kq * 4 + 1][i] = f.y;
            sb->As[kq * 4 + 2][i] = f.z; sb->As[kq * 4 + 3][i] = f.w;
        }
#pragma unroll
        for (int e = 0; e < 2; e++) {
            int li = tid + e * 256;
            int nn = li >> 2, kq = li & 3;
            float4 f = *(const float4*)&Brow[(size_t)nn * H + k0 + kq * 4];
            sb->Bs[kq * 4 + 0][nn] = f.x; sb->Bs[kq * 4 + 1][nn] = f.y;
            sb->Bs[kq * 4 + 2][nn] = f.z; sb->Bs[kq * 4 + 3][nn] = f.w;
        }
        __syncthreads();
#pragma unroll
        for (int kk = 0; kk < 16; kk++) {
            float ra[4], rb[8];
#pragma unroll
            for (int a = 0; a < 4; a++) ra[a] = sb->As[kk][tr * 4 + a];
#pragma unroll
            for (int b = 0; b < 8; b++) rb[b] = sb->Bs[kk][tc * 8 + b];
#pragma unroll
            for (int a = 0; a < 4; a++)
#pragma unroll
                for (int b = 0; b < 8; b++) acc[a][b] += ra[a] * rb[b];
        }
        __syncthreads();
    }

#pragma unroll
    for (int a = 0; a < 4; a++) {
        int i = tr * 4 + a;
        if (i >= mtile) continue;
        size_t pbase = (size_t)sb->pidx[i] * H;
#pragma unroll
        for (int b = 0; b < 8; b++) {
            int row = j0 + tc * 8 + b;
            float v = acc[a][b];
            if (PHASE == 1) {
                if (j0 < H) {
                    float z = 1.0f / (1.0f + expf(-(v + g_gz[pbase + row])));
                    g_gz[pbase + row] = z;
                } else {
                    int rrow = row - H;
                    float r = 1.0f / (1.0f + expf(-(v + g_gr[pbase + rrow])));
                    g_gr[pbase + rrow] = g_mem[pbase + rrow] * r;
                }
            } else {
                float cc = tanhf(v + g_gh[pbase + row]);
                float z = g_gz[pbase + row];
                float m = g_mem[pbase + row];
                g_ph[pbase + row] = z * m + (1.0f - z) * cc;
            }
        }
    }
    __syncthreads();
}

__global__ __launch_bounds__(256) void wave_kernel(const int* __restrict__ tree,
                                                   const float* __restrict__ Uz,
                                                   const float* __restrict__ Ur,
                                                   const float* __restrict__ Uh) {
    __shared__ union { ShA a; ShB b; } sh;
    int tid = threadIdx.x;
    int bid = blockIdx.x;
    int nb = gridDim.x;
    int nlev = g_nlev;

    for (int l = 1; l <= nlev; l++) {
        int ls = g_lstart[l];
        int le = g_lstart[l + 1];
        int Nl = le - ls;

        // ---- Phase A: attention + memory per parent ----
        for (int ii = ls + bid; ii < le; ii += nb) {
            int p = g_order[ii];
            if (tid == 0) {
                int nc = 0;
#pragma unroll
                for (int j = 0; j < DEG; j++) {
                    int c = tree[p * DEG + j];
                    if (c > -1) sh.a.cidx[nc++] = c;
                }
                sh.a.nc = nc;
            }
            __syncthreads();
            int nc = sh.a.nc;

            for (int i = 0; i < nc; i++) {
                int c = sh.a.cidx[i];
                const float* src = (c < NLEAF) ? &g_xe[(size_t)c * H]
                                               : &g_ph[(size_t)(c - NLEAF) * H];
                if (tid < 128) ((float4*)sh.a.bufA[i])[tid] = ((const float4*)src)[tid];
            }
            __syncthreads();

            float (*cur)[H] = sh.a.bufA;
            float (*nxt)[H] = sh.a.bufB;

            for (int layer = 0; layer < NLAYER; layer++) {
                int tot = HEADS * nc * nc;
                for (int t = tid; t < tot; t += 256) {
                    int hd = t / (nc * nc);
                    int r2 = t - hd * nc * nc;
                    int q = r2 / nc, k = r2 - q * nc;
                    const float* qp = &cur[q][hd * DK];
                    const float* kp = &cur[k][hd * DK];
                    float s = 0.f;
#pragma unroll 16
                    for (int d = 0; d < DK; d++) s += qp[d] * kp[d];
                    sh.a.sc[hd][q][k] = s * 0.125f;
                }
                __syncthreads();
                for (int t = tid; t < HEADS * nc; t += 256) {
                    int hd = t / nc, q = t - hd * nc;
                    float m = -1e30f;
                    for (int k = 0; k < nc; k++) m = fmaxf(m, sh.a.sc[hd][q][k]);
                    float ssum = 0.f;
                    for (int k = 0; k < nc; k++) {
                        float e = expf(sh.a.sc[hd][q][k] - m);
                        ssum += e;
                        sh.a.sc[hd][q][k] = e;
                    }
                    float inv = 1.0f / ssum;
                    for (int k = 0; k < nc; k++) sh.a.sc[hd][q][k] *= inv;
                }
                __syncthreads();
                for (int c = tid; c < H; c += 256) {
                    int hd = c >> 6;
                    for (int q = 0; q < nc; q++) {
                        float o = 0.f;
                        for (int k = 0; k < nc; k++) o += sh.a.sc[hd][q][k] * cur[k][c];
                        nxt[q][c] = o;
                    }
                }
                __syncthreads();
                float (*tmp)[H] = cur; cur = nxt; nxt = tmp;
            }
            float invn = 1.0f / (float)nc;
            for (int c = tid; c < H; c += 256) {
                float s = 0.f;
                for (int q = 0; q < nc; q++) s += cur[q][c];
                g_mem[(size_t)p * H + c] = s * invn;
            }
            __syncthreads();
        }
        grid_sync_dev(nb);

        // ---- Phase B1: z,r GEMM ----
        int ptiles = (Nl + 63) >> 6;
        int ntiles = ptiles * 8;
        for (int t = bid; t < ntiles; t += nb) {
            int pt = t >> 3;
            int j0 = (t & 7) * 128;
            int i0 = ls + pt * 64;
            int mtile = Nl - pt * 64; if (mtile > 64) mtile = 64;
            gemm_tile<1>(&sh.b, i0, mtile, j0, Uz, Ur, Uh);
        }
        grid_sync_dev(nb);

        // ---- Phase B2: c GEMM + combine ----
        ntiles = ptiles * 4;
        for (int t = bid; t < ntiles; t += nb) {
            int pt = t >> 2;
            int j0 = (t & 3) * 128;
            int i0 = ls + pt * 64;
            int mtile = Nl - pt * 64; if (mtile > 64) mtile = 64;
            gemm_tile<2>(&sh.b, i0, mtile, j0, Uz, Ur, Uh);
        }
        grid_sync_dev(nb);
    }
}

// ============================================================
__global__ void maxk_kernel() {
    int b = blockIdx.x;
    int rows_per = (NPAR + MAXB - 1) / MAXB;
    int r0 = b * rows_per;
    int r1 = min(NPAR, r0 + rows_per);
    for (int c = threadIdx.x; c < H; c += 256) {
        float m = -1e30f;
        for (int r = r0; r < r1; r++) m = fmaxf(m, g_ph[r * H + c]);
        g_pmax[b * H + c] = m;
    }
}

__global__ __launch_bounds__(512) void final_kernel(const float* __restrict__ Wout,
                                                    const float* __restrict__ bout,
                                                    float* __restrict__ out) {
    __shared__ float fin[H];
    __shared__ float logits[NCLASS];
    int tid = threadIdx.x;
    if (tid < H) {
        float m = -1e30f;
        for (int b = 0; b < MAXB; b++) m = fmaxf(m, g_pmax[b * H + tid]);
        fin[tid] = m;
    }
    __syncthreads();
    if (tid < NCLASS * 32) {
        int cls = tid >> 5, lane = tid & 31;
        float s = 0.f;
        for (int h = lane; h < H; h += 32) s += Wout[cls * H + h] * fin[h];
#pragma unroll
        for (int o = 16; o > 0; o >>= 1) s += __shfl_down_sync(0xffffffffu, s, o);
        if (lane == 0) logits[cls] = s + bout[cls];
    }
    __syncthreads();
    if (tid == 0) {
        float m = fmaxf(fmaxf(logits[0], logits[1]), fmaxf(logits[2], logits[3]));
        float e0 = expf(logits[0] - m), e1 = expf(logits[1] - m);
        float e2 = expf(logits[2] - m), e3 = expf(logits[3] - m);
        float inv = 1.0f / (e0 + e1 + e2 + e3);
        out[0] = e0 * inv; out[1] = e1 * inv; out[2] = e2 * inv; out[3] = e3 * inv;
    }
}

// ============================================================
extern "C" void kernel_launch(void* const* d_in, const int* in_sizes, int n_in,
                              void* d_out, int out_size) {
    const float* xw   = (const float*)d_in[0];
    const int*   xi   = (const int*)d_in[1];
    const int*   tree = (const int*)d_in[2];
    const float* E    = (const float*)d_in[3];
    const float* Wz   = (const float*)d_in[4];
    const float* Uz   = (const float*)d_in[5];
    const float* bz   = (const float*)d_in[6];
    const float* Wr   = (const float*)d_in[7];
    const float* Ur   = (const float*)d_in[8];
    const float* br   = (const float*)d_in[9];
    const float* Wh   = (const float*)d_in[10];
    const float* Uh   = (const float*)d_in[11];
    const float* bh   = (const float*)d_in[12];
    const float* Wout = (const float*)d_in[13];
    const float* bout = (const float*)d_in[14];

    // config (idempotent, capture-safe host APIs)
    cudaFuncSetAttribute(levels_kernel,
                         cudaFuncAttributeMaxDynamicSharedMemorySize, NPAR * 4 + 1024);
    int perSM = 0;
    cudaOccupancyMaxActiveBlocksPerMultiprocessor(&perSM, wave_kernel, 256, 0);
    if (perSM < 1) perSM = 1;
    if (perSM > 4) perSM = 4;
    int nsm = 0;
    cudaDeviceGetAttribute(&nsm, cudaDevAttrMultiProcessorCount, 0);
    if (nsm <= 0) nsm = 148;
    int grid = perSM * nsm;

    prep_kernel<<<(VOCAB * H + 255) / 256, 256>>>(E);
    xe_kernel<<<NTOT, 128>>>(xw, xi);

    dim3 gg((NPAR + BM - 1) / BM, H / BN);
    sgemm_nt<<<gg, 256>>>(Wz, bz, 0);
    sgemm_nt<<<gg, 256>>>(Wr, br, 1);
    sgemm_nt<<<gg, 256>>>(Wh, bh, 2);

    levels_kernel<<<1, 1024, NPAR * 4>>>(tree);
    wave_kernel<<<grid, 256>>>(tree, Uz, Ur, Uh);

    maxk_kernel<<<MAXB, 256>>>();
    final_kernel<<<1, 512>>>(Wout, bout, (float*)d_out);
    (void)in_sizes; (void)n_in; (void)out_size;
}